// round 3
// baseline (speedup 1.0000x reference)
#include <cuda_runtime.h>

// SpikingLayer: fused EPSP (double-exponential truncated FIR via exact
// delayed-correction recurrences, fp64 state) + f32 threshold/refractory scan.
//
// Shapes (fixed): T=500, B=16, n_syn=1, N=4096.  S = B*N = 65536.
// Layout: x[t*S + id], out[t*S + id].
//
// Exact reformulation of the reference 149-tap FIR (conv of 50-tap exp(-t/5)
// and 100-tap exp(-t/10) kernels):
//   u(t)  = a*u(t-1)  + [x(t)     - a^50 * x(t-50) ]   (correction exact in f32)
//   ul(t) = a*ul(t-1) + [x(t-100) - a^50 * x(t-150)]   == u(t-100)
//   w(t)  = b*w(t-1)  + u(t) - b^100 * ul(t)           == vmem(t)
// fp64 state => taps match the reference's float64-built kernel to ~1e-14,
// leaving only the reference's own f32 conv rounding (~1e-6) as discrepancy.
// Spike/refractory scan replicates the reference f32 op sequence exactly:
//   vt = float(w) + r;  s = (vt >= 1);  r = (r - s) * alpha_f32.

#define SNN_S 65536
#define SNN_T 500

__global__ __launch_bounds__(64, 8)
void SpikingLayer_90202903151092_kernel(const float* __restrict__ x,
                                        float* __restrict__ out) {
    const int id = blockIdx.x * 64 + threadIdx.x;   // one neuron per thread

    const double Ad   = 0.81873075307798185867;     // exp(-1/5)
    const double Bd   = 0.90483741803595957316;     // exp(-1/10)
    const double E10  = 4.5399929762484851536e-05;  // exp(-10) = a^50 = b^100
    const float  A50f = 4.5399929762484851536e-05f; // f32 copy for corrections
    const float  ALPH = 0.90483741803595957316f;    // alpha in f32 (reference scan)

    double u  = 0.0;   // synaptic FIR state
    double ul = 0.0;   // u lagged by 100
    double w  = 0.0;   // membrane FIR state (== vmem)
    float  r  = 0.0f;  // refractory state (f32, matches reference scan)

    const float* xp = x + id;
    float*       op = out + id;

    // Phase A: t in [0,50) — no delayed terms
    #pragma unroll 5
    for (int t = 0; t < 50; ++t) {
        float x0 = xp[(long)t * SNN_S];
        u = fma(Ad, u, (double)x0);
        w = fma(Bd, w, u);
        float vt = (float)w + r;
        float s  = (vt >= 1.0f) ? 1.0f : 0.0f;
        r = (r - s) * ALPH;
        op[(long)t * SNN_S] = s;
    }

    // Phase B: t in [50,100) — x(t-50) active
    #pragma unroll 5
    for (int t = 50; t < 100; ++t) {
        float x0  = xp[(long)t * SNN_S];
        float x50 = xp[(long)(t - 50) * SNN_S];
        float c1  = fmaf(-A50f, x50, x0);      // exact-ish: x binary
        u = fma(Ad, u, (double)c1);
        w = fma(Bd, w, u);
        float vt = (float)w + r;
        float s  = (vt >= 1.0f) ? 1.0f : 0.0f;
        r = (r - s) * ALPH;
        op[(long)t * SNN_S] = s;
    }

    // Phase C: t in [100,150) — x(t-100) active (lagged u starts)
    #pragma unroll 5
    for (int t = 100; t < 150; ++t) {
        float x0   = xp[(long)t * SNN_S];
        float x50  = xp[(long)(t - 50) * SNN_S];
        float x100 = xp[(long)(t - 100) * SNN_S];
        float c1   = fmaf(-A50f, x50, x0);
        u  = fma(Ad, u,  (double)c1);
        ul = fma(Ad, ul, (double)x100);
        w  = fma(Bd, w, fma(-E10, ul, u));
        float vt = (float)w + r;
        float s  = (vt >= 1.0f) ? 1.0f : 0.0f;
        r = (r - s) * ALPH;
        op[(long)t * SNN_S] = s;
    }

    // Phase D: t in [150,500) — steady state
    #pragma unroll 5
    for (int t = 150; t < SNN_T; ++t) {
        float x0   = xp[(long)t * SNN_S];
        float x50  = xp[(long)(t - 50) * SNN_S];
        float x100 = xp[(long)(t - 100) * SNN_S];
        float x150 = xp[(long)(t - 150) * SNN_S];
        float c1   = fmaf(-A50f, x50,  x0);
        float c2   = fmaf(-A50f, x150, x100);
        u  = fma(Ad, u,  (double)c1);
        ul = fma(Ad, ul, (double)c2);
        w  = fma(Bd, w, fma(-E10, ul, u));
        float vt = (float)w + r;
        float s  = (vt >= 1.0f) ? 1.0f : 0.0f;
        r = (r - s) * ALPH;
        op[(long)t * SNN_S] = s;
    }
}

extern "C" void kernel_launch(void* const* d_in, const int* in_sizes, int n_in,
                              void* d_out, int out_size) {
    const float* x = (const float*)d_in[0];   // binary_input (T,B,1,N) float32
    // d_in[1] = epsp_kernel (1,149): algebraically folded into the recurrence
    float* out = (float*)d_out;               // spikes (T,B,N) float32
    SpikingLayer_90202903151092_kernel<<<1024, 64>>>(x, out);
}